// round 4
// baseline (speedup 1.0000x reference)
#include <cuda_runtime.h>
#include <cuda_bf16.h>
#include <mma.h>
#include <cstdint>

using namespace nvcuda;

// Problem constants
#define NROWS 100000
#define DIN   1024
#define DD    512
#define NG    8
#define GS    12500

// GEMM tiling
#define BM 128
#define BN 256
#define BK 16
#define NTHREADS 512
#define LDA 24       // As stride (bf16 elems), 48B
#define LDB 264      // Bs stride (bf16 elems), 528B
#define LDCS 68      // epilogue staging stride (fp32 elems)
#define A_BYTES (BM * LDA * 2)            // 6144
#define B_BYTES (BK * LDB * 2)            // 8448
#define BUFB (2 * A_BYTES + 2 * B_BYTES)  // 29184
#define SMEM_BYTES (2 * BUFB)             // 58368
#define MTILES ((NROWS + BM - 1) / BM)    // 782
#define NSLICES (DD / BN)                 // 2

// ---------------- scratch (device globals; no allocation allowed) ----------
__device__ float    g_tmid[(size_t)NROWS * DD];   // 204.8 MB
__device__ float    g_scores[NROWS];
__device__ float    g_d[NROWS];
__device__ float    g_spart[NSLICES * NROWS];
__device__ float    g_dpart[NSLICES * NROWS];
__device__ float    g_tAA[NG * GS];
__device__ float    g_bag[NG * DD];
__device__ unsigned g_maxbits;
__device__ float    g_Z;
__device__ int      g_imax[NG];
__device__ int      g_imin[NG];

// ---------------- helpers ---------------------------------------------------
__device__ __forceinline__ float tanh_fast(float x) {
    float y;
    asm("tanh.approx.f32 %0, %1;" : "=f"(y) : "f"(x));
    return y;
}
// fp32x4 -> bf16 hi/lo split, 8B stores
__device__ __forceinline__ void split_sts4(float4 v, __nv_bfloat16* h, __nv_bfloat16* l) {
    float vv[4] = {v.x, v.y, v.z, v.w};
    __nv_bfloat16 hv[4], lv[4];
#pragma unroll
    for (int j = 0; j < 4; j++) {
        hv[j] = __float2bfloat16(vv[j]);
        lv[j] = __float2bfloat16(vv[j] - __bfloat162float(hv[j]));
    }
    *(uint2*)h = *(uint2*)hv;
    *(uint2*)l = *(uint2*)lv;
}
// fp32x8 -> bf16 hi/lo split, 16B stores
__device__ __forceinline__ void split_sts8(float4 v0, float4 v1,
                                           __nv_bfloat16* h, __nv_bfloat16* l) {
    float v[8] = {v0.x, v0.y, v0.z, v0.w, v1.x, v1.y, v1.z, v1.w};
    __nv_bfloat16 hv[8], lv[8];
#pragma unroll
    for (int j = 0; j < 8; j++) {
        hv[j] = __float2bfloat16(v[j]);
        lv[j] = __float2bfloat16(v[j] - __bfloat162float(hv[j]));
    }
    *(uint4*)h = *(uint4*)hv;
    *(uint4*)l = *(uint4*)lv;
}
// ordered-float encoding for atomicMax over signed floats
__device__ __forceinline__ unsigned enc_f(float f) {
    unsigned u = __float_as_uint(f);
    return (u & 0x80000000u) ? ~u : (u | 0x80000000u);
}
__device__ __forceinline__ float dec_f(unsigned u) {
    u = (u & 0x80000000u) ? (u & 0x7FFFFFFFu) : ~u;
    return __uint_as_float(u);
}

// ---------------- init -------------------------------------------------------
__global__ void init_kernel() {
    int tid = blockIdx.x * blockDim.x + threadIdx.x;
    if (tid == 0) { g_maxbits = 0u; g_Z = 0.f; }
    if (tid < NG * DD) g_bag[tid] = 0.f;
}

// ---------------- bf16x3 WMMA GEMM ------------------------------------------
// MODE 0: C = Ain @ Bin; epilogue: relu -> g_tmid, dpart = relu(C) . (Wc1-Wc0)
// MODE 1: A = g_tmid; epilogue: spart = sum_n tanh(C[.,n]) * watt[n]
// Tile: 128x256, BK=16, 512 threads (4x4 warps of 32x64), double-buffered.
template <int KTOT, int MODE>
__global__ void __launch_bounds__(NTHREADS, 1)
gemm_mma(const float* __restrict__ Ain, const float* __restrict__ Bin,
         const float* __restrict__ watt, const float* __restrict__ Wc) {
    extern __shared__ char dsm[];
    const float* A = (MODE == 0) ? Ain : (const float*)g_tmid;

    const int tid = threadIdx.x;
    const int wid = tid >> 5;
    const int m0 = blockIdx.x * BM;
    const int n0 = blockIdx.y * BN;

    // warp layout: 4 M-groups x 4 N-groups
    const int wm = (wid >> 2) * 32;
    const int wn = (wid & 3) * 64;

    wmma::fragment<wmma::accumulator, 16, 16, 16, float> acc[2][4];
#pragma unroll
    for (int i = 0; i < 2; i++)
#pragma unroll
        for (int n = 0; n < 4; n++) wmma::fill_fragment(acc[i][n], 0.f);

    // staging maps
    const int ar  = tid >> 2;            // A row 0..127
    const int akq = (tid & 3) * 4;       // A k offset 0/4/8/12
    const int bk  = tid >> 5;            // B k row 0..15
    const int bnq = (tid & 31) * 8;      // B n offset 0..248
    const bool aval = (m0 + ar) < NROWS;

    const float* aptr = A + (size_t)(m0 + ar) * KTOT + akq;
    const float* bptr = Bin + (size_t)bk * DD + n0 + bnq;

    float4 pa, pb0, pb1;
    pa  = aval ? *(const float4*)aptr : make_float4(0.f, 0.f, 0.f, 0.f);
    pb0 = *(const float4*)bptr;
    pb1 = *(const float4*)(bptr + 4);

    const int KC = KTOT / BK;
    for (int kc = 0; kc < KC; kc++) {
        char* buf = dsm + (kc & 1) * BUFB;
        __nv_bfloat16* Ah = (__nv_bfloat16*)buf;
        __nv_bfloat16* Al = (__nv_bfloat16*)(buf + A_BYTES);
        __nv_bfloat16* Bh = (__nv_bfloat16*)(buf + 2 * A_BYTES);
        __nv_bfloat16* Bl = (__nv_bfloat16*)(buf + 2 * A_BYTES + B_BYTES);

        split_sts4(pa, &Ah[ar * LDA + akq], &Al[ar * LDA + akq]);
        split_sts8(pb0, pb1, &Bh[bk * LDB + bnq], &Bl[bk * LDB + bnq]);
        __syncthreads();

        if (kc + 1 < KC) {
            aptr += BK;
            bptr += (size_t)BK * DD;
            if (aval) pa = *(const float4*)aptr;
            pb0 = *(const float4*)bptr;
            pb1 = *(const float4*)(bptr + 4);
        }

        // hoisted A fragments (loaded once per kc)
        wmma::fragment<wmma::matrix_a, 16, 16, 16, __nv_bfloat16, wmma::row_major> fah[2], fal[2];
#pragma unroll
        for (int i = 0; i < 2; i++) {
            wmma::load_matrix_sync(fah[i], &Ah[(wm + 16 * i) * LDA], LDA);
            wmma::load_matrix_sync(fal[i], &Al[(wm + 16 * i) * LDA], LDA);
        }
#pragma unroll
        for (int n = 0; n < 4; n++) {
            wmma::fragment<wmma::matrix_b, 16, 16, 16, __nv_bfloat16, wmma::row_major> fbh, fbl;
            wmma::load_matrix_sync(fbh, &Bh[wn + 16 * n], LDB);
            wmma::load_matrix_sync(fbl, &Bl[wn + 16 * n], LDB);
#pragma unroll
            for (int i = 0; i < 2; i++) {
                wmma::mma_sync(acc[i][n], fah[i], fbh, acc[i][n]);
                wmma::mma_sync(acc[i][n], fal[i], fbh, acc[i][n]);
                wmma::mma_sync(acc[i][n], fah[i], fbl, acc[i][n]);
            }
        }
    }

    // ---------------- epilogue: stage C in four 64-col quarters -------------
    float* Cs = (float*)dsm;            // 128 x LDCS fp32 = 34816 B
    const int row = tid >> 2;
    const int q = tid & 3;
    const int grow = m0 + row;
    float racc = 0.f;  // dacc (MODE 0) or sacc (MODE 1)

#pragma unroll
    for (int hn = 0; hn < 4; hn++) {
        __syncthreads();
        if ((wid & 3) == hn) {
#pragma unroll
            for (int i = 0; i < 2; i++)
#pragma unroll
                for (int n = 0; n < 4; n++)
                    wmma::store_matrix_sync(&Cs[(wm + 16 * i) * LDCS + 16 * n],
                                            acc[i][n], LDCS, wmma::mem_row_major);
        }
        __syncthreads();
        if (grow < NROWS) {
            const int cbase = n0 + hn * 64 + q * 16;
            if (MODE == 0) {
#pragma unroll
                for (int j = 0; j < 16; j += 4) {
                    float4 v = *(float4*)&Cs[row * LDCS + q * 16 + j];
                    v.x = fmaxf(v.x, 0.f); v.y = fmaxf(v.y, 0.f);
                    v.z = fmaxf(v.z, 0.f); v.w = fmaxf(v.w, 0.f);
                    *(float4*)&g_tmid[(size_t)grow * DD + cbase + j] = v;
                    int c = cbase + j;
                    racc = fmaf(v.x, Wc[2 * c + 1]       - Wc[2 * c],       racc);
                    racc = fmaf(v.y, Wc[2 * (c + 1) + 1] - Wc[2 * (c + 1)], racc);
                    racc = fmaf(v.z, Wc[2 * (c + 2) + 1] - Wc[2 * (c + 2)], racc);
                    racc = fmaf(v.w, Wc[2 * (c + 3) + 1] - Wc[2 * (c + 3)], racc);
                }
            } else {
#pragma unroll
                for (int j = 0; j < 16; j++) {
                    float y = Cs[row * LDCS + q * 16 + j];
                    racc = fmaf(tanh_fast(y), watt[cbase + j], racc);
                }
            }
        }
    }
    racc += __shfl_xor_sync(0xFFFFFFFFu, racc, 1);
    racc += __shfl_xor_sync(0xFFFFFFFFu, racc, 2);
    if (q == 0 && grow < NROWS) {
        if (MODE == 0)
            g_dpart[(size_t)blockIdx.y * NROWS + grow] = racc;
        else
            g_spart[(size_t)blockIdx.y * NROWS + grow] = racc;
    }
}

// ---------------- combine partials -------------------------------------------
__global__ void combine_kernel() {
    int i = blockIdx.x * blockDim.x + threadIdx.x;
    if (i < NROWS) {
        g_d[i] = g_dpart[i] + g_dpart[NROWS + i];
        g_scores[i] = g_spart[i] + g_spart[NROWS + i];
    }
}

// ---------------- global softmax reductions ---------------------------------
__global__ void red_max_kernel() {
    __shared__ float sm[256];
    float m = -1e30f;
    for (int i = blockIdx.x * blockDim.x + threadIdx.x; i < NROWS;
         i += gridDim.x * blockDim.x)
        m = fmaxf(m, g_scores[i]);
    sm[threadIdx.x] = m;
    __syncthreads();
    for (int s = 128; s > 0; s >>= 1) {
        if (threadIdx.x < s) sm[threadIdx.x] = fmaxf(sm[threadIdx.x], sm[threadIdx.x + s]);
        __syncthreads();
    }
    if (threadIdx.x == 0) atomicMax(&g_maxbits, enc_f(sm[0]));
}

__global__ void red_sum_kernel() {
    __shared__ float sm[256];
    float smax = dec_f(g_maxbits);
    float acc = 0.f;
    for (int i = blockIdx.x * blockDim.x + threadIdx.x; i < NROWS;
         i += gridDim.x * blockDim.x)
        acc += expf(g_scores[i] - smax);
    sm[threadIdx.x] = acc;
    __syncthreads();
    for (int s = 128; s > 0; s >>= 1) {
        if (threadIdx.x < s) sm[threadIdx.x] += sm[threadIdx.x + s];
        __syncthreads();
    }
    if (threadIdx.x == 0) atomicAdd(&g_Z, sm[0]);
}

// ---------------- per-group re-softmax + argmax/argmin ----------------------
#define GITER 13  // ceil(12500/1024)
__global__ __launch_bounds__(1024, 1)
void group_kernel(const int* __restrict__ idx) {
    __shared__ float sv[1024];
    __shared__ int si[1024];
    const int g = blockIdx.x;
    const int tid = threadIdx.x;
    const float smax = dec_f(g_maxbits);
    const float Z = g_Z;

    float vals[GITER];
    int js[GITER];
    float lmax = -1e30f;
#pragma unroll
    for (int t = 0; t < GITER; t++) {
        int i = tid + t * 1024;
        if (i < GS) {
            int j = idx[g * GS + i];
            float a = expf(g_scores[j] - smax) / Z;   // AA[j]
            vals[t] = a;
            js[t] = j;
            lmax = fmaxf(lmax, a);
        } else {
            vals[t] = -1e30f;
            js[t] = 0;
        }
    }
    sv[tid] = lmax;
    __syncthreads();
    for (int s = 512; s > 0; s >>= 1) {
        if (tid < s) sv[tid] = fmaxf(sv[tid], sv[tid + s]);
        __syncthreads();
    }
    float m = sv[0];
    __syncthreads();
    float lsum = 0.f;
#pragma unroll
    for (int t = 0; t < GITER; t++) {
        int i = tid + t * 1024;
        if (i < GS) lsum += expf(vals[t] - m);
    }
    sv[tid] = lsum;
    __syncthreads();
    for (int s = 512; s > 0; s >>= 1) {
        if (tid < s) sv[tid] += sv[tid + s];
        __syncthreads();
    }
    float S = sv[0];
    __syncthreads();

    float bq = -1e30f; int bi = GS;
    float wq =  1e30f; int wi = GS;
#pragma unroll
    for (int t = 0; t < GITER; t++) {
        int i = tid + t * 1024;
        if (i < GS) {
            float ta = expf(vals[t] - m) / S;
            g_tAA[g * GS + i] = ta;
            float qv = ta * g_d[js[t]];
            if (qv > bq || (qv == bq && i < bi)) { bq = qv; bi = i; }
            if (qv < wq || (qv == wq && i < wi)) { wq = qv; wi = i; }
        }
    }
    sv[tid] = bq; si[tid] = bi;
    __syncthreads();
    for (int s = 512; s > 0; s >>= 1) {
        if (tid < s) {
            float v2 = sv[tid + s]; int i2 = si[tid + s];
            if (v2 > sv[tid] || (v2 == sv[tid] && i2 < si[tid])) { sv[tid] = v2; si[tid] = i2; }
        }
        __syncthreads();
    }
    if (tid == 0) g_imax[g] = si[0];
    __syncthreads();
    sv[tid] = wq; si[tid] = wi;
    __syncthreads();
    for (int s = 512; s > 0; s >>= 1) {
        if (tid < s) {
            float v2 = sv[tid + s]; int i2 = si[tid + s];
            if (v2 < sv[tid] || (v2 == sv[tid] && i2 < si[tid])) { sv[tid] = v2; si[tid] = i2; }
        }
        __syncthreads();
    }
    if (tid == 0) g_imin[g] = si[0];
}

// ---------------- bag = sum_i tAA_i * tmid[idx_i] ---------------------------
#define BPG 64
__global__ void bag_kernel(const int* __restrict__ idx) {
    const int g = blockIdx.y;
    const int blk = blockIdx.x;
    const int tid = threadIdx.x;  // 256
    const int CH = (GS + BPG - 1) / BPG;
    int i0 = blk * CH;
    int i1 = i0 + CH; if (i1 > GS) i1 = GS;
    float a0 = 0.f, a1 = 0.f;
    for (int i = i0; i < i1; i++) {
        int j = idx[g * GS + i];
        float w = g_tAA[g * GS + i];
        const float* row = &g_tmid[(size_t)j * DD];
        a0 = fmaf(w, row[tid], a0);
        a1 = fmaf(w, row[tid + 256], a1);
    }
    atomicAdd(&g_bag[g * DD + tid], a0);
    atomicAdd(&g_bag[g * DD + tid + 256], a1);
}

// ---------------- final: preds + pseudo feats --------------------------------
__global__ void final_kernel(const float* __restrict__ Wc, const float* __restrict__ bc,
                             float* __restrict__ out) {
    const int tid = threadIdx.x;  // 512
    const int w = tid >> 5, lane = tid & 31;
    if (w < 16) {
        int g = w >> 1, c = w & 1;
        float s = 0.f;
        for (int k = lane; k < DD; k += 32)
            s = fmaf(g_bag[g * DD + k], Wc[k * 2 + c], s);
#pragma unroll
        for (int o = 16; o > 0; o >>= 1) s += __shfl_down_sync(0xFFFFFFFFu, s, o);
        if (lane == 0) out[g * 2 + c] = s + bc[c];
    }
    for (int e = tid; e < NG * 2 * DD; e += 512) {
        int g = e / (2 * DD);
        int r = (e / DD) & 1;
        int c = e % DD;
        int rowi = r ? g_imin[g] : g_imax[g];
        out[16 + e] = g_tmid[(size_t)rowi * DD + c];
    }
}

// ---------------- launch ------------------------------------------------------
extern "C" void kernel_launch(void* const* d_in, const int* in_sizes, int n_in,
                              void* d_out, int out_size) {
    const float* x    = (const float*)d_in[0];
    const int*   idx  = (const int*)d_in[1];
    const float* W1   = (const float*)d_in[2];
    const float* V    = (const float*)d_in[3];
    const float* watt = (const float*)d_in[4];
    const float* Wc   = (const float*)d_in[5];
    const float* bc   = (const float*)d_in[6];
    float* out = (float*)d_out;

    cudaFuncSetAttribute(gemm_mma<DIN, 0>,
                         cudaFuncAttributeMaxDynamicSharedMemorySize, SMEM_BYTES);
    cudaFuncSetAttribute(gemm_mma<DD, 1>,
                         cudaFuncAttributeMaxDynamicSharedMemorySize, SMEM_BYTES);

    init_kernel<<<16, 256>>>();
    gemm_mma<DIN, 0><<<dim3(MTILES, NSLICES), NTHREADS, SMEM_BYTES>>>(x, W1, watt, Wc);
    gemm_mma<DD, 1><<<dim3(MTILES, NSLICES), NTHREADS, SMEM_BYTES>>>(x, V, watt, Wc);
    combine_kernel<<<(NROWS + 255) / 256, 256>>>();
    red_max_kernel<<<256, 256>>>();
    red_sum_kernel<<<256, 256>>>();
    group_kernel<<<NG, 1024>>>(idx);
    bag_kernel<<<dim3(BPG, NG), 256>>>(idx);
    final_kernel<<<1, 512>>>(Wc, bc, out);
}

// round 5
// speedup vs baseline: 1.0238x; 1.0238x over previous
#include <cuda_runtime.h>
#include <cuda_bf16.h>
#include <mma.h>
#include <cstdint>

using namespace nvcuda;

// Problem constants
#define NROWS 100000
#define DIN   1024
#define DD    512
#define NG    8
#define GS    12500

// GEMM tiling
#define BM 128
#define BN 128
#define BK 16
#define NTHREADS 256
#define STAGES 3
#define LDA 24       // As stride in bf16 (48B), conflict-free for ldsm
#define LDB 136      // Bs stride in bf16 (272B)
#define LDCS 68      // epilogue staging stride (fp32)
#define A_BYTES (BM * LDA * 2)            // 6144
#define B_BYTES (BK * LDB * 2)            // 4352
#define BUFB (2 * A_BYTES + 2 * B_BYTES)  // 20992
#define SMEM_BYTES (STAGES * BUFB)        // 62976
#define MTILES ((NROWS + BM - 1) / BM)    // 782
#define NSLICES (DD / BN)                 // 4

// ---------------- scratch (device globals; no allocation allowed) ----------
__device__ __nv_bfloat16 g_xh[(size_t)NROWS * DIN];
__device__ __nv_bfloat16 g_xl[(size_t)NROWS * DIN];
__device__ __nv_bfloat16 g_th[(size_t)NROWS * DD];
__device__ __nv_bfloat16 g_tl[(size_t)NROWS * DD];
__device__ __nv_bfloat16 g_W1h[DIN * DD], g_W1l[DIN * DD];
__device__ __nv_bfloat16 g_Vh[DD * DD],  g_Vl[DD * DD];
__device__ float    g_scores[NROWS];
__device__ float    g_d[NROWS];
__device__ float    g_spart[NSLICES * NROWS];
__device__ float    g_dpart[NSLICES * NROWS];
__device__ float    g_tAA[NG * GS];
__device__ float    g_bag[NG * DD];
__device__ unsigned g_maxbits;
__device__ float    g_Z;
__device__ int      g_imax[NG];
__device__ int      g_imin[NG];

// ---------------- helpers ---------------------------------------------------
__device__ __forceinline__ float tanh_fast(float x) {
    float y;
    asm("tanh.approx.f32 %0, %1;" : "=f"(y) : "f"(x));
    return y;
}
__device__ __forceinline__ void cp_async16(uint32_t dst, const void* src, bool pred) {
    int sz = pred ? 16 : 0;
    asm volatile("cp.async.cg.shared.global [%0], [%1], 16, %2;\n"
                 :: "r"(dst), "l"(src), "r"(sz));
}
__device__ __forceinline__ void cp_commit() {
    asm volatile("cp.async.commit_group;\n" ::: "memory");
}
template <int N>
__device__ __forceinline__ void cp_wait() {
    asm volatile("cp.async.wait_group %0;\n" :: "n"(N) : "memory");
}
// ordered-float encoding for atomicMax over signed floats
__device__ __forceinline__ unsigned enc_f(float f) {
    unsigned u = __float_as_uint(f);
    return (u & 0x80000000u) ? ~u : (u | 0x80000000u);
}
__device__ __forceinline__ float dec_f(unsigned u) {
    u = (u & 0x80000000u) ? (u & 0x7FFFFFFFu) : ~u;
    return __uint_as_float(u);
}

// ---------------- prep: pre-split x, W1, V into bf16 hi/lo ------------------
__global__ void prep_kernel(const float* __restrict__ x, const float* __restrict__ W1,
                            const float* __restrict__ V) {
    int t = blockIdx.x * blockDim.x + threadIdx.x;
    int stride = gridDim.x * blockDim.x;
    // x
    for (int i = t; i < NROWS * DIN / 4; i += stride) {
        float4 v = ((const float4*)x)[i];
        float vv[4] = {v.x, v.y, v.z, v.w};
        __nv_bfloat16 h[4], l[4];
#pragma unroll
        for (int j = 0; j < 4; j++) {
            h[j] = __float2bfloat16(vv[j]);
            l[j] = __float2bfloat16(vv[j] - __bfloat162float(h[j]));
        }
        ((uint2*)g_xh)[i] = *(uint2*)h;
        ((uint2*)g_xl)[i] = *(uint2*)l;
    }
    // W1
    for (int i = t; i < DIN * DD / 4; i += stride) {
        float4 v = ((const float4*)W1)[i];
        float vv[4] = {v.x, v.y, v.z, v.w};
        __nv_bfloat16 h[4], l[4];
#pragma unroll
        for (int j = 0; j < 4; j++) {
            h[j] = __float2bfloat16(vv[j]);
            l[j] = __float2bfloat16(vv[j] - __bfloat162float(h[j]));
        }
        ((uint2*)g_W1h)[i] = *(uint2*)h;
        ((uint2*)g_W1l)[i] = *(uint2*)l;
    }
    // V
    for (int i = t; i < DD * DD / 4; i += stride) {
        float4 v = ((const float4*)V)[i];
        float vv[4] = {v.x, v.y, v.z, v.w};
        __nv_bfloat16 h[4], l[4];
#pragma unroll
        for (int j = 0; j < 4; j++) {
            h[j] = __float2bfloat16(vv[j]);
            l[j] = __float2bfloat16(vv[j] - __bfloat162float(h[j]));
        }
        ((uint2*)g_Vh)[i] = *(uint2*)h;
        ((uint2*)g_Vl)[i] = *(uint2*)l;
    }
    if (t < NG * DD) g_bag[t] = 0.f;
    if (t == 0) { g_maxbits = 0u; g_Z = 0.f; }
}

// ---------------- bf16x3 WMMA GEMM, cp.async 3-stage pipeline ---------------
// MODE 0: C = x @ W1 (K=1024); epilogue: relu -> (g_th,g_tl), dpart = C.relu . (Wc1-Wc0)
// MODE 1: C = tmid @ V (K=512); epilogue: spart = sum_n tanh(C[.,n]) * watt[n]
template <int KTOT, int MODE>
__global__ void __launch_bounds__(NTHREADS, 2)
gemm_mma(const float* __restrict__ watt, const float* __restrict__ Wc) {
    extern __shared__ char dsm[];
    const __nv_bfloat16* Agh = (MODE == 0) ? g_xh : g_th;
    const __nv_bfloat16* Agl = (MODE == 0) ? g_xl : g_tl;
    const __nv_bfloat16* Bgh = (MODE == 0) ? g_W1h : g_Vh;
    const __nv_bfloat16* Bgl = (MODE == 0) ? g_W1l : g_Vl;

    const int tid = threadIdx.x;
    const int wid = tid >> 5;
    const int m0 = blockIdx.x * BM;
    const int n0 = blockIdx.y * BN;

    // warp layout: 4 M-groups x 2 N-groups; warp tile 32x64
    const int wm = (wid >> 1) * 32;
    const int wn = (wid & 1) * 64;

    wmma::fragment<wmma::accumulator, 16, 16, 16, float> acc[2][4];
#pragma unroll
    for (int i = 0; i < 2; i++)
#pragma unroll
        for (int n = 0; n < 4; n++) wmma::fill_fragment(acc[i][n], 0.f);

    // staging maps
    const int arow = tid >> 1, ach = tid & 1;     // A: 128 rows x 2 chunks
    const int brow = tid >> 4, bch = tid & 15;    // B: 16 rows x 16 chunks
    const bool aval = (m0 + arow) < NROWS;
    const int arowc = aval ? (m0 + arow) : (NROWS - 1);
    const uint32_t sb0 = (uint32_t)__cvta_generic_to_shared(dsm);

    auto issue = [&](int kcs) {
        const uint32_t sb = sb0 + (kcs % STAGES) * BUFB;
        size_t ga = (size_t)arowc * KTOT + kcs * BK + ach * 8;
        cp_async16(sb + arow * 48 + ach * 16, Agh + ga, aval);
        cp_async16(sb + A_BYTES + arow * 48 + ach * 16, Agl + ga, aval);
        size_t gb = (size_t)(kcs * BK + brow) * DD + n0 + bch * 8;
        cp_async16(sb + 2 * A_BYTES + brow * 272 + bch * 16, Bgh + gb, true);
        cp_async16(sb + 2 * A_BYTES + B_BYTES + brow * 272 + bch * 16, Bgl + gb, true);
        cp_commit();
    };

    const int KC = KTOT / BK;
#pragma unroll
    for (int s = 0; s < STAGES - 1; s++) issue(s);

    for (int kc = 0; kc < KC; kc++) {
        cp_wait<STAGES - 2>();
        __syncthreads();
        if (kc + STAGES - 1 < KC) issue(kc + STAGES - 1);

        char* buf = dsm + (kc % STAGES) * BUFB;
        __nv_bfloat16* Ah = (__nv_bfloat16*)buf;
        __nv_bfloat16* Al = (__nv_bfloat16*)(buf + A_BYTES);
        __nv_bfloat16* Bh = (__nv_bfloat16*)(buf + 2 * A_BYTES);
        __nv_bfloat16* Bl = (__nv_bfloat16*)(buf + 2 * A_BYTES + B_BYTES);

        wmma::fragment<wmma::matrix_a, 16, 16, 16, __nv_bfloat16, wmma::row_major> fah[2], fal[2];
#pragma unroll
        for (int i = 0; i < 2; i++) {
            wmma::load_matrix_sync(fah[i], &Ah[(wm + 16 * i) * LDA], LDA);
            wmma::load_matrix_sync(fal[i], &Al[(wm + 16 * i) * LDA], LDA);
        }
#pragma unroll
        for (int n = 0; n < 4; n++) {
            wmma::fragment<wmma::matrix_b, 16, 16, 16, __nv_bfloat16, wmma::row_major> fbh, fbl;
            wmma::load_matrix_sync(fbh, &Bh[wn + 16 * n], LDB);
            wmma::load_matrix_sync(fbl, &Bl[wn + 16 * n], LDB);
#pragma unroll
            for (int i = 0; i < 2; i++) {
                wmma::mma_sync(acc[i][n], fah[i], fbh, acc[i][n]);
                wmma::mma_sync(acc[i][n], fal[i], fbh, acc[i][n]);
                wmma::mma_sync(acc[i][n], fah[i], fbl, acc[i][n]);
            }
        }
        __syncthreads();
    }
    cp_wait<0>();
    __syncthreads();

    // ---------------- epilogue: stage C in two 64-col halves ----------------
    float* Cs = (float*)dsm;            // 128 x LDCS fp32 = 34816 B
    const int row = tid >> 1;
    const int q = tid & 1;
    const int grow = m0 + row;
    float racc = 0.f;

#pragma unroll
    for (int hn = 0; hn < 2; hn++) {
        __syncthreads();
        if ((wid & 1) == hn) {
#pragma unroll
            for (int i = 0; i < 2; i++)
#pragma unroll
                for (int n = 0; n < 4; n++)
                    wmma::store_matrix_sync(&Cs[(wm + 16 * i) * LDCS + 16 * n],
                                            acc[i][n], LDCS, wmma::mem_row_major);
        }
        __syncthreads();
        if (grow < NROWS) {
            const int cbase = n0 + hn * 64 + q * 32;
            if (MODE == 0) {
#pragma unroll
                for (int j = 0; j < 32; j += 4) {
                    float4 v = *(float4*)&Cs[row * LDCS + q * 32 + j];
                    float vv[4] = {fmaxf(v.x, 0.f), fmaxf(v.y, 0.f),
                                   fmaxf(v.z, 0.f), fmaxf(v.w, 0.f)};
                    __nv_bfloat16 h[4], l[4];
                    int c = cbase + j;
#pragma unroll
                    for (int e = 0; e < 4; e++) {
                        h[e] = __float2bfloat16(vv[e]);
                        l[e] = __float2bfloat16(vv[e] - __bfloat162float(h[e]));
                        racc = fmaf(vv[e], Wc[2 * (c + e) + 1] - Wc[2 * (c + e)], racc);
                    }
                    *(uint2*)&g_th[(size_t)grow * DD + c] = *(uint2*)h;
                    *(uint2*)&g_tl[(size_t)grow * DD + c] = *(uint2*)l;
                }
            } else {
#pragma unroll
                for (int j = 0; j < 32; j++) {
                    float y = Cs[row * LDCS + q * 32 + j];
                    racc = fmaf(tanh_fast(y), watt[cbase + j], racc);
                }
            }
        }
    }
    racc += __shfl_xor_sync(0xFFFFFFFFu, racc, 1);
    if (q == 0 && grow < NROWS) {
        if (MODE == 0)
            g_dpart[(size_t)blockIdx.y * NROWS + grow] = racc;
        else
            g_spart[(size_t)blockIdx.y * NROWS + grow] = racc;
    }
}

// ---------------- combine partials -------------------------------------------
__global__ void combine_kernel() {
    int i = blockIdx.x * blockDim.x + threadIdx.x;
    if (i < NROWS) {
        g_d[i] = (g_dpart[i] + g_dpart[NROWS + i]) +
                 (g_dpart[2 * NROWS + i] + g_dpart[3 * NROWS + i]);
        g_scores[i] = (g_spart[i] + g_spart[NROWS + i]) +
                      (g_spart[2 * NROWS + i] + g_spart[3 * NROWS + i]);
    }
}

// ---------------- global softmax reductions ---------------------------------
__global__ void red_max_kernel() {
    __shared__ float sm[256];
    float m = -1e30f;
    for (int i = blockIdx.x * blockDim.x + threadIdx.x; i < NROWS;
         i += gridDim.x * blockDim.x)
        m = fmaxf(m, g_scores[i]);
    sm[threadIdx.x] = m;
    __syncthreads();
    for (int s = 128; s > 0; s >>= 1) {
        if (threadIdx.x < s) sm[threadIdx.x] = fmaxf(sm[threadIdx.x], sm[threadIdx.x + s]);
        __syncthreads();
    }
    if (threadIdx.x == 0) atomicMax(&g_maxbits, enc_f(sm[0]));
}

__global__ void red_sum_kernel() {
    __shared__ float sm[256];
    float smax = dec_f(g_maxbits);
    float acc = 0.f;
    for (int i = blockIdx.x * blockDim.x + threadIdx.x; i < NROWS;
         i += gridDim.x * blockDim.x)
        acc += expf(g_scores[i] - smax);
    sm[threadIdx.x] = acc;
    __syncthreads();
    for (int s = 128; s > 0; s >>= 1) {
        if (threadIdx.x < s) sm[threadIdx.x] += sm[threadIdx.x + s];
        __syncthreads();
    }
    if (threadIdx.x == 0) atomicAdd(&g_Z, sm[0]);
}

// ---------------- per-group re-softmax + argmax/argmin ----------------------
#define GITER 13  // ceil(12500/1024)
__global__ __launch_bounds__(1024, 1)
void group_kernel(const int* __restrict__ idx) {
    __shared__ float sv[1024];
    __shared__ int si[1024];
    const int g = blockIdx.x;
    const int tid = threadIdx.x;
    const float smax = dec_f(g_maxbits);
    const float Z = g_Z;

    float vals[GITER];
    int js[GITER];
    float lmax = -1e30f;
#pragma unroll
    for (int t = 0; t < GITER; t++) {
        int i = tid + t * 1024;
        if (i < GS) {
            int j = idx[g * GS + i];
            float a = expf(g_scores[j] - smax) / Z;
            vals[t] = a;
            js[t] = j;
            lmax = fmaxf(lmax, a);
        } else {
            vals[t] = -1e30f;
            js[t] = 0;
        }
    }
    sv[tid] = lmax;
    __syncthreads();
    for (int s = 512; s > 0; s >>= 1) {
        if (tid < s) sv[tid] = fmaxf(sv[tid], sv[tid + s]);
        __syncthreads();
    }
    float m = sv[0];
    __syncthreads();
    float lsum = 0.f;
#pragma unroll
    for (int t = 0; t < GITER; t++) {
        int i = tid + t * 1024;
        if (i < GS) lsum += expf(vals[t] - m);
    }
    sv[tid] = lsum;
    __syncthreads();
    for (int s = 512; s > 0; s >>= 1) {
        if (tid < s) sv[tid] += sv[tid + s];
        __syncthreads();
    }
    float S = sv[0];
    __syncthreads();

    float bq = -1e30f; int bi = GS;
    float wq =  1e30f; int wi = GS;
#pragma unroll
    for (int t = 0; t < GITER; t++) {
        int i = tid + t * 1024;
        if (i < GS) {
            float ta = expf(vals[t] - m) / S;
            g_tAA[g * GS + i] = ta;
            float qv = ta * g_d[js[t]];
            if (qv > bq || (qv == bq && i < bi)) { bq = qv; bi = i; }
            if (qv < wq || (qv == wq && i < wi)) { wq = qv; wi = i; }
        }
    }
    sv[tid] = bq; si[tid] = bi;
    __syncthreads();
    for (int s = 512; s > 0; s >>= 1) {
        if (tid < s) {
            float v2 = sv[tid + s]; int i2 = si[tid + s];
            if (v2 > sv[tid] || (v2 == sv[tid] && i2 < si[tid])) { sv[tid] = v2; si[tid] = i2; }
        }
        __syncthreads();
    }
    if (tid == 0) g_imax[g] = si[0];
    __syncthreads();
    sv[tid] = wq; si[tid] = wi;
    __syncthreads();
    for (int s = 512; s > 0; s >>= 1) {
        if (tid < s) {
            float v2 = sv[tid + s]; int i2 = si[tid + s];
            if (v2 < sv[tid] || (v2 == sv[tid] && i2 < si[tid])) { sv[tid] = v2; si[tid] = i2; }
        }
        __syncthreads();
    }
    if (tid == 0) g_imin[g] = si[0];
}

// ---------------- bag = sum_i tAA_i * tmid[idx_i] ---------------------------
#define BPG 64
__global__ void bag_kernel(const int* __restrict__ idx) {
    const int g = blockIdx.y;
    const int blk = blockIdx.x;
    const int tid = threadIdx.x;  // 256
    const int CH = (GS + BPG - 1) / BPG;
    int i0 = blk * CH;
    int i1 = i0 + CH; if (i1 > GS) i1 = GS;
    float a0 = 0.f, a1 = 0.f;
    for (int i = i0; i < i1; i++) {
        int j = idx[g * GS + i];
        float w = g_tAA[g * GS + i];
        size_t base = (size_t)j * DD;
        float v0 = __bfloat162float(g_th[base + tid]) + __bfloat162float(g_tl[base + tid]);
        float v1 = __bfloat162float(g_th[base + tid + 256]) +
                   __bfloat162float(g_tl[base + tid + 256]);
        a0 = fmaf(w, v0, a0);
        a1 = fmaf(w, v1, a1);
    }
    atomicAdd(&g_bag[g * DD + tid], a0);
    atomicAdd(&g_bag[g * DD + tid + 256], a1);
}

// ---------------- final: preds + pseudo feats --------------------------------
__global__ void final_kernel(const float* __restrict__ Wc, const float* __restrict__ bc,
                             float* __restrict__ out) {
    const int tid = threadIdx.x;  // 512
    const int w = tid >> 5, lane = tid & 31;
    if (w < 16) {
        int g = w >> 1, c = w & 1;
        float s = 0.f;
        for (int k = lane; k < DD; k += 32)
            s = fmaf(g_bag[g * DD + k], Wc[k * 2 + c], s);
#pragma unroll
        for (int o = 16; o > 0; o >>= 1) s += __shfl_down_sync(0xFFFFFFFFu, s, o);
        if (lane == 0) out[g * 2 + c] = s + bc[c];
    }
    for (int e = tid; e < NG * 2 * DD; e += 512) {
        int g = e / (2 * DD);
        int r = (e / DD) & 1;
        int c = e % DD;
        int rowi = r ? g_imin[g] : g_imax[g];
        size_t base = (size_t)rowi * DD + c;
        out[16 + e] = __bfloat162float(g_th[base]) + __bfloat162float(g_tl[base]);
    }
}

// ---------------- launch ------------------------------------------------------
extern "C" void kernel_launch(void* const* d_in, const int* in_sizes, int n_in,
                              void* d_out, int out_size) {
    const float* x    = (const float*)d_in[0];
    const int*   idx  = (const int*)d_in[1];
    const float* W1   = (const float*)d_in[2];
    const float* V    = (const float*)d_in[3];
    const float* watt = (const float*)d_in[4];
    const float* Wc   = (const float*)d_in[5];
    const float* bc   = (const float*)d_in[6];
    float* out = (float*)d_out;

    cudaFuncSetAttribute(gemm_mma<DIN, 0>,
                         cudaFuncAttributeMaxDynamicSharedMemorySize, SMEM_BYTES);
    cudaFuncSetAttribute(gemm_mma<DD, 1>,
                         cudaFuncAttributeMaxDynamicSharedMemorySize, SMEM_BYTES);

    prep_kernel<<<2048, 256>>>(x, W1, V);
    gemm_mma<DIN, 0><<<dim3(MTILES, NSLICES), NTHREADS, SMEM_BYTES>>>(watt, Wc);
    gemm_mma<DD, 1><<<dim3(MTILES, NSLICES), NTHREADS, SMEM_BYTES>>>(watt, Wc);
    combine_kernel<<<(NROWS + 255) / 256, 256>>>();
    red_max_kernel<<<256, 256>>>();
    red_sum_kernel<<<256, 256>>>();
    group_kernel<<<NG, 1024>>>(idx);
    bag_kernel<<<dim3(BPG, NG), 256>>>(idx);
    final_kernel<<<1, 512>>>(Wc, bc, out);
}

// round 6
// speedup vs baseline: 2.7511x; 2.6872x over previous
#include <cuda_runtime.h>
#include <cuda_fp16.h>
#include <mma.h>
#include <cstdint>

using namespace nvcuda;

// Problem constants
#define NROWS 100000
#define DIN   1024
#define DD    512
#define NG    8
#define GS    12500

// GEMM tiling
#define BM 128
#define BN 128
#define BK 16
#define NTHREADS 256
#define STAGES 4
#define LDA 24       // As stride in halfs (48B), padded for conflict-free ldsm
#define LDB 136      // Bs stride in halfs (272B)
#define LDCS 68      // epilogue staging stride (fp32)
#define A_BYTES (BM * LDA * 2)            // 6144
#define B_BYTES (BK * LDB * 2)            // 4352
#define BUFB (A_BYTES + B_BYTES)          // 10496
#define SMEM_BYTES (STAGES * BUFB)        // 41984 (< 48KB default)
#define MTILES ((NROWS + BM - 1) / BM)    // 782
#define NSLICES (DD / BN)                 // 4

// ---------------- scratch (device globals; no allocation allowed) ----------
__device__ __half g_xh[(size_t)NROWS * DIN];   // 200 MB
__device__ __half g_th[(size_t)NROWS * DD];    // 100 MB (tmid, fp16)
__device__ __half g_W1h[DIN * DD];
__device__ __half g_Vh[DD * DD];
__device__ float    g_scores[NROWS];
__device__ float    g_d[NROWS];
__device__ float    g_spart[NSLICES * NROWS];
__device__ float    g_dpart[NSLICES * NROWS];
__device__ float    g_tAA[NG * GS];
__device__ float    g_bag[NG * DD];
__device__ unsigned g_maxbits;
__device__ float    g_Z;
__device__ int      g_imax[NG];
__device__ int      g_imin[NG];

// ---------------- helpers ---------------------------------------------------
__device__ __forceinline__ float tanh_fast(float x) {
    float y;
    asm("tanh.approx.f32 %0, %1;" : "=f"(y) : "f"(x));
    return y;
}
__device__ __forceinline__ void cp_async16(uint32_t dst, const void* src, bool pred) {
    int sz = pred ? 16 : 0;
    asm volatile("cp.async.cg.shared.global [%0], [%1], 16, %2;\n"
                 :: "r"(dst), "l"(src), "r"(sz));
}
__device__ __forceinline__ void cp_commit() {
    asm volatile("cp.async.commit_group;\n" ::: "memory");
}
template <int N>
__device__ __forceinline__ void cp_wait() {
    asm volatile("cp.async.wait_group %0;\n" :: "n"(N) : "memory");
}
// ordered-float encoding for atomicMax over signed floats
__device__ __forceinline__ unsigned enc_f(float f) {
    unsigned u = __float_as_uint(f);
    return (u & 0x80000000u) ? ~u : (u | 0x80000000u);
}
__device__ __forceinline__ float dec_f(unsigned u) {
    u = (u & 0x80000000u) ? (u & 0x7FFFFFFFu) : ~u;
    return __uint_as_float(u);
}

// ---------------- prep: convert x, W1, V to fp16 ----------------------------
__global__ void prep_kernel(const float* __restrict__ x, const float* __restrict__ W1,
                            const float* __restrict__ V) {
    int t = blockIdx.x * blockDim.x + threadIdx.x;
    int stride = gridDim.x * blockDim.x;
    for (int i = t; i < NROWS * DIN / 4; i += stride) {
        float4 v = ((const float4*)x)[i];
        __half h[4] = {__float2half(v.x), __float2half(v.y),
                       __float2half(v.z), __float2half(v.w)};
        ((uint2*)g_xh)[i] = *(uint2*)h;
    }
    for (int i = t; i < DIN * DD / 4; i += stride) {
        float4 v = ((const float4*)W1)[i];
        __half h[4] = {__float2half(v.x), __float2half(v.y),
                       __float2half(v.z), __float2half(v.w)};
        ((uint2*)g_W1h)[i] = *(uint2*)h;
    }
    for (int i = t; i < DD * DD / 4; i += stride) {
        float4 v = ((const float4*)V)[i];
        __half h[4] = {__float2half(v.x), __float2half(v.y),
                       __float2half(v.z), __float2half(v.w)};
        ((uint2*)g_Vh)[i] = *(uint2*)h;
    }
    if (t < NG * DD) g_bag[t] = 0.f;
    if (t == 0) { g_maxbits = 0u; g_Z = 0.f; }
}

// ---------------- fp16 WMMA GEMM, cp.async 4-stage pipeline -----------------
// MODE 0: C = x @ W1 (K=1024); epilogue: relu -> g_th (fp16), dpart = relu(C).(Wc1-Wc0)
// MODE 1: C = tmid @ V (K=512); epilogue: spart = sum_n tanh(C[.,n]) * watt[n]
template <int KTOT, int MODE>
__global__ void __launch_bounds__(NTHREADS, 2)
gemm_mma(const float* __restrict__ watt, const float* __restrict__ Wc) {
    extern __shared__ char dsm[];
    const __half* Ag = (MODE == 0) ? g_xh : g_th;
    const __half* Bg = (MODE == 0) ? g_W1h : g_Vh;

    const int tid = threadIdx.x;
    const int wid = tid >> 5;
    const int m0 = blockIdx.x * BM;
    const int n0 = blockIdx.y * BN;

    // warp layout: 4 M-groups x 2 N-groups; warp tile 32x64
    const int wm = (wid >> 1) * 32;
    const int wn = (wid & 1) * 64;

    wmma::fragment<wmma::accumulator, 16, 16, 16, float> acc[2][4];
#pragma unroll
    for (int i = 0; i < 2; i++)
#pragma unroll
        for (int n = 0; n < 4; n++) wmma::fill_fragment(acc[i][n], 0.f);

    // staging maps: A tile 128x16 halfs (32B/row -> 2x16B), B tile 16x128 (256B/row -> 16x16B)
    const int arow = tid >> 1, ach = tid & 1;
    const int brow = tid >> 4, bch = tid & 15;
    const bool aval = (m0 + arow) < NROWS;
    const int arowc = aval ? (m0 + arow) : (NROWS - 1);
    const uint32_t sb0 = (uint32_t)__cvta_generic_to_shared(dsm);

    auto issue = [&](int kcs) {
        const uint32_t sb = sb0 + (kcs % STAGES) * BUFB;
        size_t ga = (size_t)arowc * KTOT + kcs * BK + ach * 8;
        cp_async16(sb + arow * 48 + ach * 16, Ag + ga, aval);
        size_t gb = (size_t)(kcs * BK + brow) * DD + n0 + bch * 8;
        cp_async16(sb + A_BYTES + brow * 272 + bch * 16, Bg + gb, true);
        cp_commit();
    };

    const int KC = KTOT / BK;
#pragma unroll
    for (int s = 0; s < STAGES - 1; s++) issue(s);

    for (int kc = 0; kc < KC; kc++) {
        cp_wait<STAGES - 2>();
        __syncthreads();
        if (kc + STAGES - 1 < KC) issue(kc + STAGES - 1);

        char* buf = dsm + (kc % STAGES) * BUFB;
        __half* As = (__half*)buf;
        __half* Bs = (__half*)(buf + A_BYTES);

        wmma::fragment<wmma::matrix_a, 16, 16, 16, __half, wmma::row_major> fa[2];
#pragma unroll
        for (int i = 0; i < 2; i++)
            wmma::load_matrix_sync(fa[i], &As[(wm + 16 * i) * LDA], LDA);
#pragma unroll
        for (int n = 0; n < 4; n++) {
            wmma::fragment<wmma::matrix_b, 16, 16, 16, __half, wmma::row_major> fb;
            wmma::load_matrix_sync(fb, &Bs[wn + 16 * n], LDB);
#pragma unroll
            for (int i = 0; i < 2; i++)
                wmma::mma_sync(acc[i][n], fa[i], fb, acc[i][n]);
        }
        __syncthreads();
    }
    cp_wait<0>();
    __syncthreads();

    // ---------------- epilogue: stage C in two 64-col halves ----------------
    float* Cs = (float*)dsm;            // 128 x LDCS fp32 = 34816 B < 41984
    const int row = tid >> 1;
    const int q = tid & 1;
    const int grow = m0 + row;
    float racc = 0.f;

#pragma unroll
    for (int hn = 0; hn < 2; hn++) {
        __syncthreads();
        if ((wid & 1) == hn) {
#pragma unroll
            for (int i = 0; i < 2; i++)
#pragma unroll
                for (int n = 0; n < 4; n++)
                    wmma::store_matrix_sync(&Cs[(wm + 16 * i) * LDCS + 16 * n],
                                            acc[i][n], LDCS, wmma::mem_row_major);
        }
        __syncthreads();
        if (grow < NROWS) {
            const int cbase = n0 + hn * 64 + q * 32;
            if (MODE == 0) {
#pragma unroll
                for (int j = 0; j < 32; j += 4) {
                    float4 v = *(float4*)&Cs[row * LDCS + q * 32 + j];
                    float vv[4] = {fmaxf(v.x, 0.f), fmaxf(v.y, 0.f),
                                   fmaxf(v.z, 0.f), fmaxf(v.w, 0.f)};
                    __half h[4];
                    int c = cbase + j;
#pragma unroll
                    for (int e = 0; e < 4; e++) {
                        h[e] = __float2half(vv[e]);
                        racc = fmaf(vv[e], Wc[2 * (c + e) + 1] - Wc[2 * (c + e)], racc);
                    }
                    *(uint2*)&g_th[(size_t)grow * DD + c] = *(uint2*)h;
                }
            } else {
#pragma unroll
                for (int j = 0; j < 32; j++) {
                    float y = Cs[row * LDCS + q * 32 + j];
                    racc = fmaf(tanh_fast(y), watt[cbase + j], racc);
                }
            }
        }
    }
    racc += __shfl_xor_sync(0xFFFFFFFFu, racc, 1);
    if (q == 0 && grow < NROWS) {
        if (MODE == 0)
            g_dpart[(size_t)blockIdx.y * NROWS + grow] = racc;
        else
            g_spart[(size_t)blockIdx.y * NROWS + grow] = racc;
    }
}

// ---------------- combine partials -------------------------------------------
__global__ void combine_kernel() {
    int i = blockIdx.x * blockDim.x + threadIdx.x;
    if (i < NROWS) {
        g_d[i] = (g_dpart[i] + g_dpart[NROWS + i]) +
                 (g_dpart[2 * NROWS + i] + g_dpart[3 * NROWS + i]);
        g_scores[i] = (g_spart[i] + g_spart[NROWS + i]) +
                      (g_spart[2 * NROWS + i] + g_spart[3 * NROWS + i]);
    }
}

// ---------------- global softmax reductions ---------------------------------
__global__ void red_max_kernel() {
    __shared__ float sm[256];
    float m = -1e30f;
    for (int i = blockIdx.x * blockDim.x + threadIdx.x; i < NROWS;
         i += gridDim.x * blockDim.x)
        m = fmaxf(m, g_scores[i]);
    sm[threadIdx.x] = m;
    __syncthreads();
    for (int s = 128; s > 0; s >>= 1) {
        if (threadIdx.x < s) sm[threadIdx.x] = fmaxf(sm[threadIdx.x], sm[threadIdx.x + s]);
        __syncthreads();
    }
    if (threadIdx.x == 0) atomicMax(&g_maxbits, enc_f(sm[0]));
}

__global__ void red_sum_kernel() {
    __shared__ float sm[256];
    float smax = dec_f(g_maxbits);
    float acc = 0.f;
    for (int i = blockIdx.x * blockDim.x + threadIdx.x; i < NROWS;
         i += gridDim.x * blockDim.x)
        acc += expf(g_scores[i] - smax);
    sm[threadIdx.x] = acc;
    __syncthreads();
    for (int s = 128; s > 0; s >>= 1) {
        if (threadIdx.x < s) sm[threadIdx.x] += sm[threadIdx.x + s];
        __syncthreads();
    }
    if (threadIdx.x == 0) atomicAdd(&g_Z, sm[0]);
}

// ---------------- per-group re-softmax + argmax/argmin ----------------------
#define GITER 13  // ceil(12500/1024)
__global__ __launch_bounds__(1024, 1)
void group_kernel(const int* __restrict__ idx) {
    __shared__ float sv[1024];
    __shared__ int si[1024];
    const int g = blockIdx.x;
    const int tid = threadIdx.x;
    const float smax = dec_f(g_maxbits);
    const float Z = g_Z;

    float vals[GITER];
    int js[GITER];
    float lmax = -1e30f;
#pragma unroll
    for (int t = 0; t < GITER; t++) {
        int i = tid + t * 1024;
        if (i < GS) {
            int j = idx[g * GS + i];
            float a = expf(g_scores[j] - smax) / Z;
            vals[t] = a;
            js[t] = j;
            lmax = fmaxf(lmax, a);
        } else {
            vals[t] = -1e30f;
            js[t] = 0;
        }
    }
    sv[tid] = lmax;
    __syncthreads();
    for (int s = 512; s > 0; s >>= 1) {
        if (tid < s) sv[tid] = fmaxf(sv[tid], sv[tid + s]);
        __syncthreads();
    }
    float m = sv[0];
    __syncthreads();
    float lsum = 0.f;
#pragma unroll
    for (int t = 0; t < GITER; t++) {
        int i = tid + t * 1024;
        if (i < GS) lsum += expf(vals[t] - m);
    }
    sv[tid] = lsum;
    __syncthreads();
    for (int s = 512; s > 0; s >>= 1) {
        if (tid < s) sv[tid] += sv[tid + s];
        __syncthreads();
    }
    float S = sv[0];
    __syncthreads();

    float bq = -1e30f; int bi = GS;
    float wq =  1e30f; int wi = GS;
#pragma unroll
    for (int t = 0; t < GITER; t++) {
        int i = tid + t * 1024;
        if (i < GS) {
            float ta = expf(vals[t] - m) / S;
            g_tAA[g * GS + i] = ta;
            float qv = ta * g_d[js[t]];
            if (qv > bq || (qv == bq && i < bi)) { bq = qv; bi = i; }
            if (qv < wq || (qv == wq && i < wi)) { wq = qv; wi = i; }
        }
    }
    sv[tid] = bq; si[tid] = bi;
    __syncthreads();
    for (int s = 512; s > 0; s >>= 1) {
        if (tid < s) {
            float v2 = sv[tid + s]; int i2 = si[tid + s];
            if (v2 > sv[tid] || (v2 == sv[tid] && i2 < si[tid])) { sv[tid] = v2; si[tid] = i2; }
        }
        __syncthreads();
    }
    if (tid == 0) g_imax[g] = si[0];
    __syncthreads();
    sv[tid] = wq; si[tid] = wi;
    __syncthreads();
    for (int s = 512; s > 0; s >>= 1) {
        if (tid < s) {
            float v2 = sv[tid + s]; int i2 = si[tid + s];
            if (v2 < sv[tid] || (v2 == sv[tid] && i2 < si[tid])) { sv[tid] = v2; si[tid] = i2; }
        }
        __syncthreads();
    }
    if (tid == 0) g_imin[g] = si[0];
}

// ---------------- bag = sum_i tAA_i * tmid[idx_i] ---------------------------
#define BPG 64
__global__ void bag_kernel(const int* __restrict__ idx) {
    const int g = blockIdx.y;
    const int blk = blockIdx.x;
    const int tid = threadIdx.x;  // 256
    const int CH = (GS + BPG - 1) / BPG;
    int i0 = blk * CH;
    int i1 = i0 + CH; if (i1 > GS) i1 = GS;
    float a0 = 0.f, a1 = 0.f;
    for (int i = i0; i < i1; i++) {
        int j = idx[g * GS + i];
        float w = g_tAA[g * GS + i];
        size_t base = (size_t)j * DD;
        a0 = fmaf(w, __half2float(g_th[base + tid]), a0);
        a1 = fmaf(w, __half2float(g_th[base + tid + 256]), a1);
    }
    atomicAdd(&g_bag[g * DD + tid], a0);
    atomicAdd(&g_bag[g * DD + tid + 256], a1);
}

// ---------------- final: preds + pseudo feats --------------------------------
__global__ void final_kernel(const float* __restrict__ Wc, const float* __restrict__ bc,
                             float* __restrict__ out) {
    const int tid = threadIdx.x;  // 512
    const int w = tid >> 5, lane = tid & 31;
    if (w < 16) {
        int g = w >> 1, c = w & 1;
        float s = 0.f;
        for (int k = lane; k < DD; k += 32)
            s = fmaf(g_bag[g * DD + k], Wc[k * 2 + c], s);
#pragma unroll
        for (int o = 16; o > 0; o >>= 1) s += __shfl_down_sync(0xFFFFFFFFu, s, o);
        if (lane == 0) out[g * 2 + c] = s + bc[c];
    }
    for (int e = tid; e < NG * 2 * DD; e += 512) {
        int g = e / (2 * DD);
        int r = (e / DD) & 1;
        int c = e % DD;
        int rowi = r ? g_imin[g] : g_imax[g];
        out[16 + e] = __half2float(g_th[(size_t)rowi * DD + c]);
    }
}

// ---------------- launch ------------------------------------------------------
extern "C" void kernel_launch(void* const* d_in, const int* in_sizes, int n_in,
                              void* d_out, int out_size) {
    const float* x    = (const float*)d_in[0];
    const int*   idx  = (const int*)d_in[1];
    const float* W1   = (const float*)d_in[2];
    const float* V    = (const float*)d_in[3];
    const float* watt = (const float*)d_in[4];
    const float* Wc   = (const float*)d_in[5];
    const float* bc   = (const float*)d_in[6];
    float* out = (float*)d_out;

    prep_kernel<<<2048, 256>>>(x, W1, V);
    gemm_mma<DIN, 0><<<dim3(MTILES, NSLICES), NTHREADS, SMEM_BYTES>>>(watt, Wc);
    gemm_mma<DD, 1><<<dim3(MTILES, NSLICES), NTHREADS, SMEM_BYTES>>>(watt, Wc);
    combine_kernel<<<(NROWS + 255) / 256, 256>>>();
    red_max_kernel<<<256, 256>>>();
    red_sum_kernel<<<256, 256>>>();
    group_kernel<<<NG, 1024>>>(idx);
    bag_kernel<<<dim3(BPG, NG), 256>>>(idx);
    final_kernel<<<1, 512>>>(Wc, bc, out);
}